// round 6
// baseline (speedup 1.0000x reference)
#include <cuda_runtime.h>
#include <cstdint>

#define D 128
#define NODES_MAX 131072
#define EDGES_MAX 1100000

// ---- static device scratch (no allocations allowed) ----
__device__ unsigned int g_cnt[NODES_MAX];
__device__ unsigned int g_start[NODES_MAX + 1];
__device__ unsigned int g_cursor[NODES_MAX];
__device__ uint2        g_payload[EDGES_MAX];   // {edge_id, src}

__device__ __forceinline__ bool detect_i64(const void* p, long long n_nodes) {
    const long long* s64 = (const long long*)p;
    bool ok = true;
#pragma unroll
    for (int i = 0; i < 8; i++) {
        long long v = s64[i];
        if (v < 0 || v >= n_nodes) ok = false;
    }
    return ok;
}

__global__ void k_zero_cnt(int n) {
    int i = blockIdx.x * blockDim.x + threadIdx.x;
    if (i < n) g_cnt[i] = 0u;
}

__global__ void k_hist(const void* __restrict__ dstp, int E, long long n_nodes) {
    __shared__ int sh;
    if (threadIdx.x == 0) sh = detect_i64(dstp, n_nodes) ? 1 : 0;
    __syncthreads();
    int e = blockIdx.x * blockDim.x + threadIdx.x;
    if (e < E) {
        unsigned int d = sh ? (unsigned int)((const long long*)dstp)[e]
                            : (unsigned int)((const int*)dstp)[e];
        atomicAdd(&g_cnt[d], 1u);
    }
}

// single-block exclusive scan of g_cnt[0..n) -> g_start, g_cursor; g_start[n]=total
__global__ void k_scan(int n) {
    __shared__ unsigned int sh[1024];
    int t = threadIdx.x;
    int per = (n + 1023) >> 10;
    int lo = t * per;
    int hi = min(lo + per, n);
    unsigned int s = 0;
    for (int i = lo; i < hi; i++) s += g_cnt[i];
    sh[t] = s;
    __syncthreads();
#pragma unroll
    for (int dd = 1; dd < 1024; dd <<= 1) {
        unsigned int v = (t >= dd) ? sh[t - dd] : 0u;
        __syncthreads();
        sh[t] += v;
        __syncthreads();
    }
    unsigned int off = (t > 0) ? sh[t - 1] : 0u;
    for (int i = lo; i < hi; i++) {
        unsigned int c = g_cnt[i];
        g_start[i]  = off;
        g_cursor[i] = off;
        off += c;
    }
    if (t == 0) g_start[n] = sh[1023];
}

__global__ void k_scatter(const void* __restrict__ srcp,
                          const void* __restrict__ dstp,
                          int E, long long n_nodes) {
    __shared__ int sh;
    if (threadIdx.x == 0) sh = detect_i64(srcp, n_nodes) ? 1 : 0;
    __syncthreads();
    int e = blockIdx.x * blockDim.x + threadIdx.x;
    if (e < E) {
        unsigned int s, d;
        if (sh) {
            s = (unsigned int)((const long long*)srcp)[e];
            d = (unsigned int)((const long long*)dstp)[e];
        } else {
            s = (unsigned int)((const int*)srcp)[e];
            d = (unsigned int)((const int*)dstp)[e];
        }
        unsigned int pos = atomicAdd(&g_cursor[d], 1u);
        g_payload[pos] = make_uint2((unsigned int)e, s);
    }
}

// one warp owns one destination node: register accumulation, single streaming store
__global__ __launch_bounds__(256)
void k_main(const float* __restrict__ x,
            const float* __restrict__ y,
            const float* __restrict__ coeffs,
            float* __restrict__ out,
            int n_nodes)
{
    int gid  = blockIdx.x * blockDim.x + threadIdx.x;
    int node = gid >> 5;
    if (node >= n_nodes) return;
    int lane = gid & 31;
    int col  = lane << 2;

    unsigned int beg = g_start[node];
    unsigned int end = g_start[node + 1];
    float c = __ldg(coeffs + (lane >> 3));

    float4 a0 = make_float4(0.f, 0.f, 0.f, 0.f);
    float4 a1 = make_float4(0.f, 0.f, 0.f, 0.f);

    unsigned int i = beg;
    for (; i + 1 < end; i += 2) {            // 2 independent chains -> MLP
        uint2 p0 = g_payload[i];
        uint2 p1 = g_payload[i + 1];
        float4 y0 = __ldcs(reinterpret_cast<const float4*>(y + (size_t)p0.x * D + col));
        float4 y1 = __ldcs(reinterpret_cast<const float4*>(y + (size_t)p1.x * D + col));
        float4 x0 = __ldg (reinterpret_cast<const float4*>(x + (size_t)p0.y * D + col));
        float4 x1 = __ldg (reinterpret_cast<const float4*>(x + (size_t)p1.y * D + col));
        a0.x += x0.x * y0.x;  a0.y += x0.y * y0.y;
        a0.z += x0.z * y0.z;  a0.w += x0.w * y0.w;
        a1.x += x1.x * y1.x;  a1.y += x1.y * y1.y;
        a1.z += x1.z * y1.z;  a1.w += x1.w * y1.w;
    }
    if (i < end) {
        uint2 p0 = g_payload[i];
        float4 y0 = __ldcs(reinterpret_cast<const float4*>(y + (size_t)p0.x * D + col));
        float4 x0 = __ldg (reinterpret_cast<const float4*>(x + (size_t)p0.y * D + col));
        a0.x += x0.x * y0.x;  a0.y += x0.y * y0.y;
        a0.z += x0.z * y0.z;  a0.w += x0.w * y0.w;
    }

    float4 r;
    r.x = (a0.x + a1.x) * c;
    r.y = (a0.y + a1.y) * c;
    r.z = (a0.z + a1.z) * c;
    r.w = (a0.w + a1.w) * c;

    // exclusive owner -> plain streaming store (no atomics, no L2 pollution)
    __stcs(reinterpret_cast<float4*>(out + (size_t)node * D + col), r);
}

extern "C" void kernel_launch(void* const* d_in, const int* in_sizes, int n_in,
                              void* d_out, int out_size) {
    const float* x      = (const float*)d_in[0];
    const float* y      = (const float*)d_in[1];
    const float* coeffs = (const float*)d_in[2];
    const void*  src    = d_in[3];
    const void*  dst    = d_in[4];
    float* out = (float*)d_out;

    int E = in_sizes[1] / D;
    int n_nodes = out_size / D;

    k_zero_cnt<<<(n_nodes + 255) / 256, 256>>>(n_nodes);
    k_hist<<<(E + 255) / 256, 256>>>(dst, E, (long long)n_nodes);
    k_scan<<<1, 1024>>>(n_nodes);
    k_scatter<<<(E + 255) / 256, 256>>>(src, dst, E, (long long)n_nodes);

    long long total_threads = (long long)n_nodes * 32;
    int blocks = (int)((total_threads + 255) / 256);
    k_main<<<blocks, 256>>>(x, y, coeffs, out, n_nodes);
}

// round 7
// speedup vs baseline: 1.3454x; 1.3454x over previous
#include <cuda_runtime.h>
#include <cstdint>

#define D 128
#define EPT 4      // edges per warp
#define NPASS 2    // dst-range passes; active out per pass ~25.6MB -> L2-resident

__global__ __launch_bounds__(256)
void tp_scatter_kernel(const float* __restrict__ x,
                       const float* __restrict__ y,
                       const float* __restrict__ coeffs,
                       const void* __restrict__ srcp,
                       const void* __restrict__ dstp,
                       float* __restrict__ out,
                       int E, long long n_nodes,
                       unsigned int dlo, unsigned int dhi)
{
    // ---- index dtype detection, once per block (uniform, L2-hit broadcast)
    __shared__ int sh_i64;
    if (threadIdx.x == 0) {
        const long long* s64 = (const long long*)srcp;
        bool ok = true;
#pragma unroll
        for (int i = 0; i < 8; i++) {
            long long v = s64[i];
            if (v < 0 || v >= n_nodes) ok = false;
        }
        sh_i64 = ok ? 1 : 0;
    }
    __syncthreads();
    const bool i64 = (sh_i64 != 0);

    int gid  = blockIdx.x * blockDim.x + threadIdx.x;
    int warp = gid >> 5;
    int lane = gid & 31;
    int col  = lane << 2;                  // 16B chunk per lane
    int e0   = warp * EPT;
    if (e0 >= E) return;

    // ---- 1) index loads + pass predicate
    unsigned int s[EPT], d[EPT];
    bool act[EPT];
#pragma unroll
    for (int k = 0; k < EPT; k++) {
        int e = e0 + k;
        if (e < E) {
            if (i64) {
                s[k] = (unsigned int)((const long long*)srcp)[e];
                d[k] = (unsigned int)((const long long*)dstp)[e];
            } else {
                s[k] = (unsigned int)((const int*)srcp)[e];
                d[k] = (unsigned int)((const int*)dstp)[e];
            }
            act[k] = (d[k] >= dlo) & (d[k] < dhi);
        } else { s[k] = 0; d[k] = 0; act[k] = false; }
    }

    float c = __ldg(coeffs + (lane >> 3)); // segment = lane/8

    // ---- 2) y: streamed once across all passes -> .cs keeps x + active out in L2
    float4 yv[EPT];
#pragma unroll
    for (int k = 0; k < EPT; k++) {
        if (act[k])
            yv[k] = __ldcs(reinterpret_cast<const float4*>(y + (size_t)(e0 + k) * D + col));
    }

    // ---- 3) x gathers: independent L2-hit chains (MLP)
    float4 xv[EPT];
#pragma unroll
    for (int k = 0; k < EPT; k++) {
        if (act[k])
            xv[k] = __ldg(reinterpret_cast<const float4*>(x + (size_t)s[k] * D + col));
    }

    // ---- 4) fused multiply + fire-and-forget vector reduction
#pragma unroll
    for (int k = 0; k < EPT; k++) {
        if (act[k]) {
            float px = xv[k].x * yv[k].x * c;
            float py = xv[k].y * yv[k].y * c;
            float pz = xv[k].z * yv[k].z * c;
            float pw = xv[k].w * yv[k].w * c;
            float* addr = out + (size_t)d[k] * D + col;
            asm volatile("red.global.add.v4.f32 [%0], {%1, %2, %3, %4};"
                         :: "l"(addr), "f"(px), "f"(py), "f"(pz), "f"(pw)
                         : "memory");
        }
    }
}

extern "C" void kernel_launch(void* const* d_in, const int* in_sizes, int n_in,
                              void* d_out, int out_size) {
    const float* x      = (const float*)d_in[0];
    const float* y      = (const float*)d_in[1];
    const float* coeffs = (const float*)d_in[2];
    const void*  src    = d_in[3];
    const void*  dst    = d_in[4];
    float* out = (float*)d_out;

    int E = in_sizes[1] / D;
    int n_nodes = out_size / D;

    // zero the poisoned output via a graph-capturable memset node
    cudaMemsetAsync(d_out, 0, (size_t)out_size * sizeof(float), 0);

    int warps  = (E + EPT - 1) / EPT;
    long long total_threads = (long long)warps * 32;
    int blocks = (int)((total_threads + 255) / 256);

    // dst-range passes: each pass's active out slice stays L2-resident
    unsigned int step = (unsigned int)((n_nodes + NPASS - 1) / NPASS);
    for (int p = 0; p < NPASS; p++) {
        unsigned int dlo = (unsigned int)p * step;
        unsigned int dhi = (p == NPASS - 1) ? (unsigned int)n_nodes : dlo + step;
        tp_scatter_kernel<<<blocks, 256>>>(x, y, coeffs, src, dst, out,
                                           E, (long long)n_nodes, dlo, dhi);
    }
}

// round 8
// speedup vs baseline: 2.0209x; 1.5021x over previous
#include <cuda_runtime.h>
#include <cstdint>

#define D 128
#define WE 8        // edges per warp per pass (2 edges concurrently x 4 iterations)
#define HALF 64     // columns per pass

__global__ __launch_bounds__(256)
void tp_half_kernel(const float* __restrict__ x,
                    const float* __restrict__ y,
                    const float* __restrict__ coeffs,
                    const void* __restrict__ srcp,
                    const void* __restrict__ dstp,
                    float* __restrict__ out,
                    int E, long long n_nodes, int pass)
{
    // ---- index dtype detection, once per block (uniform, L2-hit broadcast)
    __shared__ int sh_i64;
    if (threadIdx.x == 0) {
        const long long* s64 = (const long long*)srcp;
        bool ok = true;
#pragma unroll
        for (int i = 0; i < 8; i++) {
            long long v = s64[i];
            if (v < 0 || v >= n_nodes) ok = false;
        }
        sh_i64 = ok ? 1 : 0;
    }
    __syncthreads();
    const bool i64 = (sh_i64 != 0);

    int gid  = blockIdx.x * blockDim.x + threadIdx.x;
    int warp = gid >> 5;
    int lane = gid & 31;
    int sub  = lane >> 4;                    // which of 2 concurrent edges
    int l16  = lane & 15;
    int col  = pass * HALF + (l16 << 2);     // 16B chunk within this pass's half-row
    int e0   = warp * WE;
    if (e0 >= E) return;

    // ---- 1) index loads up front (4 independent chains per thread)
    unsigned int s[4], d[4];
    bool v[4];
#pragma unroll
    for (int k = 0; k < 4; k++) {
        int e = e0 + (k << 1) + sub;
        v[k] = (e < E);
        if (v[k]) {
            if (i64) {
                s[k] = (unsigned int)((const long long*)srcp)[e];
                d[k] = (unsigned int)((const long long*)dstp)[e];
            } else {
                s[k] = (unsigned int)((const int*)srcp)[e];
                d[k] = (unsigned int)((const int*)dstp)[e];
            }
        } else { s[k] = 0; d[k] = 0; }
    }

    // segment = col/32 ; per-pass base segment = pass*2
    float c = __ldg(coeffs + (pass << 1) + (l16 >> 3));

    // ---- 2) y: streamed once total (half-row this pass) -> .cs evict-first
    float4 yv[4];
#pragma unroll
    for (int k = 0; k < 4; k++) {
        int e = e0 + (k << 1) + sub;
        yv[k] = __ldcs(reinterpret_cast<const float4*>(
                     y + (size_t)min(e, E - 1) * D + col));
    }

    // ---- 3) x gathers: 4 independent chains; active x half stays L2-resident
    float4 xv[4];
#pragma unroll
    for (int k = 0; k < 4; k++) {
        xv[k] = __ldg(reinterpret_cast<const float4*>(x + (size_t)s[k] * D + col));
    }

    // ---- 4) fused multiply + fire-and-forget vector reduction
#pragma unroll
    for (int k = 0; k < 4; k++) {
        if (v[k]) {
            float px = xv[k].x * yv[k].x * c;
            float py = xv[k].y * yv[k].y * c;
            float pz = xv[k].z * yv[k].z * c;
            float pw = xv[k].w * yv[k].w * c;
            float* addr = out + (size_t)d[k] * D + col;
            asm volatile("red.global.add.v4.f32 [%0], {%1, %2, %3, %4};"
                         :: "l"(addr), "f"(px), "f"(py), "f"(pz), "f"(pw)
                         : "memory");
        }
    }
}

extern "C" void kernel_launch(void* const* d_in, const int* in_sizes, int n_in,
                              void* d_out, int out_size) {
    const float* x      = (const float*)d_in[0];
    const float* y      = (const float*)d_in[1];
    const float* coeffs = (const float*)d_in[2];
    const void*  src    = d_in[3];
    const void*  dst    = d_in[4];
    float* out = (float*)d_out;

    int E = in_sizes[1] / D;
    long long n_nodes = (long long)(out_size / D);

    // zero the poisoned output via a graph-capturable memset node
    cudaMemsetAsync(d_out, 0, (size_t)out_size * sizeof(float), 0);

    int warps  = (E + WE - 1) / WE;                 // 125k warps per pass
    long long total_threads = (long long)warps * 32;
    int blocks = (int)((total_threads + 255) / 256);

    // column-half passes: every edge active every pass (full MLP),
    // active out+x footprint per pass ~51MB -> L2-resident, churn eliminated
    tp_half_kernel<<<blocks, 256>>>(x, y, coeffs, src, dst, out, E, n_nodes, 0);
    tp_half_kernel<<<blocks, 256>>>(x, y, coeffs, src, dst, out, E, n_nodes, 1);
}

// round 9
// speedup vs baseline: 2.2334x; 1.1051x over previous
#include <cuda_runtime.h>
#include <cstdint>

#define D 128
#define WE 8        // edges per warp per pass
#define HALF 64     // columns per pass

__global__ __launch_bounds__(128, 12)
void tp_fused_kernel(const float* __restrict__ x,
                     const float* __restrict__ y,
                     const float* __restrict__ coeffs,
                     const void* __restrict__ srcp,
                     const void* __restrict__ dstp,
                     float* __restrict__ out,
                     int E, long long n_nodes, int warps_per_pass)
{
    // ---- index dtype detection, once per block (uniform, L2-hit broadcast)
    __shared__ int sh_i64;
    if (threadIdx.x == 0) {
        const long long* s64 = (const long long*)srcp;
        bool ok = true;
#pragma unroll
        for (int i = 0; i < 8; i++) {
            long long v = s64[i];
            if (v < 0 || v >= n_nodes) ok = false;
        }
        sh_i64 = ok ? 1 : 0;
    }
    __syncthreads();
    const bool i64 = (sh_i64 != 0);

    int gid   = blockIdx.x * blockDim.x + threadIdx.x;
    int gwarp = gid >> 5;
    // blocks dispatch in order: first half of grid = pass 0, second = pass 1,
    // so the per-pass L2 hot sets stay temporally separated while the
    // pass boundary overlaps (no launch gap, no ramp bubble).
    int pass  = (gwarp >= warps_per_pass) ? 1 : 0;
    int warp  = gwarp - pass * warps_per_pass;
    int lane  = gid & 31;
    int sub   = lane >> 4;                    // which of 2 concurrent edges
    int l16   = lane & 15;
    int col   = pass * HALF + (l16 << 2);     // 16B chunk in this pass's half-row
    int e0    = warp * WE;
    if (e0 >= E) return;

    // ---- 1) index loads up front (4 independent chains per thread)
    unsigned int s[4], d[4];
    bool v[4];
#pragma unroll
    for (int k = 0; k < 4; k++) {
        int e = e0 + (k << 1) + sub;
        v[k] = (e < E);
        if (v[k]) {
            if (i64) {
                s[k] = (unsigned int)((const long long*)srcp)[e];
                d[k] = (unsigned int)((const long long*)dstp)[e];
            } else {
                s[k] = (unsigned int)((const int*)srcp)[e];
                d[k] = (unsigned int)((const int*)dstp)[e];
            }
        } else { s[k] = 0; d[k] = 0; }
    }

    // segment = col/32 ; per-pass base segment = pass*2
    float c = __ldg(coeffs + (pass << 1) + (l16 >> 3));

    // ---- 2) y: streamed once total -> .cs evict-first
    float4 yv[4];
#pragma unroll
    for (int k = 0; k < 4; k++) {
        int e = e0 + (k << 1) + sub;
        yv[k] = __ldcs(reinterpret_cast<const float4*>(
                     y + (size_t)min(e, E - 1) * D + col));
    }

    // ---- 3) x gathers: 4 independent chains; active x half stays L2-resident
    float4 xv[4];
#pragma unroll
    for (int k = 0; k < 4; k++) {
        xv[k] = __ldg(reinterpret_cast<const float4*>(x + (size_t)s[k] * D + col));
    }

    // ---- 4) fused multiply + fire-and-forget vector reduction
#pragma unroll
    for (int k = 0; k < 4; k++) {
        if (v[k]) {
            float px = xv[k].x * yv[k].x * c;
            float py = xv[k].y * yv[k].y * c;
            float pz = xv[k].z * yv[k].z * c;
            float pw = xv[k].w * yv[k].w * c;
            float* addr = out + (size_t)d[k] * D + col;
            asm volatile("red.global.add.v4.f32 [%0], {%1, %2, %3, %4};"
                         :: "l"(addr), "f"(px), "f"(py), "f"(pz), "f"(pw)
                         : "memory");
        }
    }
}

extern "C" void kernel_launch(void* const* d_in, const int* in_sizes, int n_in,
                              void* d_out, int out_size) {
    const float* x      = (const float*)d_in[0];
    const float* y      = (const float*)d_in[1];
    const float* coeffs = (const float*)d_in[2];
    const void*  src    = d_in[3];
    const void*  dst    = d_in[4];
    float* out = (float*)d_out;

    int E = in_sizes[1] / D;
    long long n_nodes = (long long)(out_size / D);

    // zero the poisoned output via a graph-capturable memset node
    cudaMemsetAsync(d_out, 0, (size_t)out_size * sizeof(float), 0);

    int warps_per_pass = (E + WE - 1) / WE;            // 125k warps per pass
    long long total_threads = (long long)warps_per_pass * 2 * 32;
    int blocks = (int)((total_threads + 127) / 128);

    tp_fused_kernel<<<blocks, 128>>>(x, y, coeffs, src, dst, out,
                                     E, n_nodes, warps_per_pass);
}